// round 2
// baseline (speedup 1.0000x reference)
#include <cuda_runtime.h>
#include <cuda_bf16.h>

// LocalLoadBalancingLoss: B=65536 rows, T=792 tunnels, D=99 dests, L=16 links.
// loss = mean_b[ var_{ddof=1}(u_b) + 0.5 * max(u_b) ],  u = linkTraffic/(cap+1e-8)

#define NUM_T 792
#define NUM_D 99
#define NUM_L 16
#define ROWS 32            // rows per tile / block
#define THREADS 512        // 16 warps: warp = link, lane = row
#define PSTRIDE 793        // odd stride -> conflict-free LDS across rows
#define MAX_BLOCKS 4096

__device__ int   g_pidx[NUM_T];     // packed: tunnel | (dest<<16), sorted by link
__device__ int   g_off[NUM_L + 1];  // CSR offsets per link
__device__ float g_invcap[NUM_L];
__device__ float g_partials[MAX_BLOCKS];

// ---------------------------------------------------------------------------
// Setup: build link-sorted CSR of tunnels (uniform across batch). 64 threads:
// (chunk c in 0..3 of 198 tunnels) x (link l in 0..15).
// ---------------------------------------------------------------------------
__global__ void llb_setup_kernel(const int* __restrict__ t2l,
                                 const float* __restrict__ cap) {
    __shared__ int cnt[4][NUM_L];
    __shared__ int start[4][NUM_L];
    __shared__ int soff[NUM_L + 1];
    const int tid = threadIdx.x;          // 64 threads
    const int c = tid >> 4;
    const int l = tid & 15;

    int k = 0;
    #pragma unroll 8
    for (int i = 0; i < 198; i++)
        if (t2l[c * 198 + i] == l) k++;
    cnt[c][l] = k;
    __syncthreads();

    if (tid == 0) {
        int acc = 0;
        for (int ll = 0; ll < NUM_L; ll++) {
            soff[ll] = acc;
            int s = acc;
            for (int cc = 0; cc < 4; cc++) { start[cc][ll] = s; s += cnt[cc][ll]; }
            acc = s;
        }
        soff[NUM_L] = acc;   // == 792
    }
    __syncthreads();

    if (tid < NUM_L + 1) g_off[tid] = soff[tid];
    if (tid < NUM_L)     g_invcap[tid] = 1.0f / (cap[tid] + 1e-8f);

    int w = start[c][l];
    for (int i = 0; i < 198; i++) {
        int t = c * 198 + i;
        if (t2l[t] == l) g_pidx[w++] = t | ((t >> 3) << 16);
    }
}

// ---------------------------------------------------------------------------
// Main: one block = 32 rows. Phase A stages tile to shared (coalesced global,
// conflict-free STS). Phase B: warp w accumulates link w for all 32 rows
// (lane = row), conflict-free LDS gathers. Then per-row stats + block partial.
// ---------------------------------------------------------------------------
__global__ __launch_bounds__(THREADS, 2)
void llb_main_kernel(const float* __restrict__ pred,
                     const float* __restrict__ dem) {
    extern __shared__ float smem[];
    float* sh_pred = smem;                       // ROWS * PSTRIDE floats
    float* sh_dem  = smem + ROWS * PSTRIDE;      // ROWS * NUM_D floats (reused as u)

    const int tid  = threadIdx.x;
    const long long tile = blockIdx.x;

    // ---- Phase A: coalesced stage-in ----
    const float* gp = pred + tile * (ROWS * NUM_T);
    #pragma unroll 4
    for (int i = tid; i < ROWS * NUM_T; i += THREADS) {
        int r = i / NUM_T;              // row of this element
        sh_pred[i + r] = gp[i];         // row*793 + col == i + r
    }
    const float* gd = dem + tile * (ROWS * NUM_D);
    #pragma unroll 2
    for (int i = tid; i < ROWS * NUM_D; i += THREADS)
        sh_dem[i] = gd[i];
    __syncthreads();

    // ---- Phase B: per-(row,link) sums ----
    const int link = tid >> 5;          // warp id
    const int row  = tid & 31;          // lane id
    const int beg = g_off[link];
    const int end = g_off[link + 1];
    const float* pr = sh_pred + row * PSTRIDE;
    const float* dm = sh_dem  + row * NUM_D;

    float s0 = 0.f, s1 = 0.f;
    int j = beg;
    #pragma unroll 2
    for (; j + 1 < end; j += 2) {
        int p0 = g_pidx[j];
        int p1 = g_pidx[j + 1];
        s0 += pr[p0 & 0xFFFF] * dm[p0 >> 16];
        s1 += pr[p1 & 0xFFFF] * dm[p1 >> 16];
    }
    if (j < end) {
        int p0 = g_pidx[j];
        s0 += pr[p0 & 0xFFFF] * dm[p0 >> 16];
    }
    const float u = (s0 + s1) * g_invcap[link];

    __syncthreads();                    // everyone done reading sh_dem
    float* sh_u = sh_dem;               // reuse: [ROWS][17] padded
    sh_u[row * 17 + link] = u;
    __syncthreads();

    // ---- per-row stats by warp 0 (lane = row) ----
    if (tid < 32) {
        const int r = tid;
        float ssum = 0.f, mx = -1e30f;
        #pragma unroll
        for (int l = 0; l < NUM_L; l++) {
            float x = sh_u[r * 17 + l];
            ssum += x;
            mx = fmaxf(mx, x);
        }
        const float mean = ssum * (1.0f / NUM_L);
        float var = 0.f;
        #pragma unroll
        for (int l = 0; l < NUM_L; l++) {
            float d = sh_u[r * 17 + l] - mean;
            var += d * d;
        }
        var *= (1.0f / (NUM_L - 1));    // ddof = 1
        float part = var + 0.5f * mx;
        #pragma unroll
        for (int o = 16; o > 0; o >>= 1)
            part += __shfl_down_sync(0xFFFFFFFFu, part, o);
        if (tid == 0) g_partials[blockIdx.x] = part;
    }
}

// ---------------------------------------------------------------------------
// Deterministic final reduction: 1 block, fixed-order strided + tree.
// ---------------------------------------------------------------------------
__global__ void llb_reduce_kernel(float* __restrict__ out, int nblocks, float inv_batch) {
    __shared__ float sb[1024];
    const int tid = threadIdx.x;
    float v = 0.f;
    for (int i = tid; i < nblocks; i += 1024)
        v += g_partials[i];
    sb[tid] = v;
    __syncthreads();
    #pragma unroll
    for (int s = 512; s > 0; s >>= 1) {
        if (tid < s) sb[tid] += sb[tid + s];
        __syncthreads();
    }
    if (tid == 0) out[0] = sb[0] * inv_batch;
}

extern "C" void kernel_launch(void* const* d_in, const int* in_sizes, int n_in,
                              void* d_out, int out_size) {
    const float* pred = (const float*)d_in[0];   // [B, 792]
    const float* dem  = (const float*)d_in[1];   // [B, 99]
    const int*   t2l  = (const int*)d_in[2];     // [792]
    const float* cap  = (const float*)d_in[3];   // [16]
    float* out = (float*)d_out;

    const int B = in_sizes[1] / NUM_D;           // 65536
    const int nblocks = B / ROWS;                // 2048

    static bool attr_set = false;
    const int smem_bytes = (ROWS * PSTRIDE + ROWS * NUM_D) * (int)sizeof(float); // 114176
    if (!attr_set) {
        cudaFuncSetAttribute(llb_main_kernel,
                             cudaFuncAttributeMaxDynamicSharedMemorySize, smem_bytes);
        attr_set = true;
    }

    llb_setup_kernel<<<1, 64>>>(t2l, cap);
    llb_main_kernel<<<nblocks, THREADS, smem_bytes>>>(pred, dem);
    llb_reduce_kernel<<<1, 1024>>>(out, nblocks, 1.0f / (float)B);
}

// round 5
// speedup vs baseline: 1.3909x; 1.3909x over previous
#include <cuda_runtime.h>
#include <cuda_bf16.h>

// LocalLoadBalancingLoss: B=65536 rows, T=792 tunnels, D=99 dests, L=16 links.
// loss = mean_b[ var_{ddof=1}(u_b) + 0.5 * max(u_b) ],  u = linkTraffic/(cap+1e-8)

#define NUM_T 792
#define NUM_D 99
#define NUM_L 16
#define ROWS 32            // rows per tile / block
#define THREADS 512        // 16 warps: warp = link, lane = row
#define PSTRIDE 793        // odd stride -> conflict-free LDS across rows
#define MAX_BLOCKS 4096
#define SETUP_THREADS 800  // 25 warps covering 792 tunnels

__device__ unsigned short g_pidx16[NUM_T];  // tunnel ids, sorted by link (dest = t>>3)
__device__ int   g_off[NUM_L + 1];          // CSR offsets per link
__device__ float g_invcap[NUM_L];
__device__ float g_partials[MAX_BLOCKS];

// ---------------------------------------------------------------------------
// Setup: build link-sorted CSR of tunnel ids. Deterministic rank via
// __match_any_sync within warps + per-link prefix over warps. ~1.5us.
// ---------------------------------------------------------------------------
__global__ void llb_setup_kernel(const int* __restrict__ t2l,
                                 const float* __restrict__ cap) {
    __shared__ int s_wcnt[25][NUM_L];   // becomes exclusive prefix over warps
    __shared__ int s_tot[NUM_L];
    __shared__ int s_off[NUM_L + 1];

    const int tid  = threadIdx.x;       // 800 threads = 25 full warps
    const int w    = tid >> 5;
    const int lane = tid & 31;
    const bool act = (tid < NUM_T);

    if (tid < 25 * NUM_L) ((int*)s_wcnt)[tid] = 0;

    const int l = act ? t2l[tid] : 0;
    // unique value for inactive lanes so they form singleton groups
    const int val = act ? l : (100 + lane);
    __syncthreads();

    unsigned m = __match_any_sync(0xFFFFFFFFu, val);
    const int rank_in_warp = __popc(m & ((1u << lane) - 1u));
    if (act && lane == (__ffs(m) - 1))
        s_wcnt[w][l] = __popc(m);
    __syncthreads();

    if (tid < NUM_L) {
        int acc = 0;
        for (int ww = 0; ww < 25; ww++) {
            int c = s_wcnt[ww][tid];
            s_wcnt[ww][tid] = acc;      // exclusive prefix
            acc += c;
        }
        s_tot[tid] = acc;
    }
    __syncthreads();

    if (tid == 0) {
        int a = 0;
        for (int ll = 0; ll < NUM_L; ll++) { s_off[ll] = a; a += s_tot[ll]; }
        s_off[NUM_L] = a;               // == 792
    }
    __syncthreads();

    if (act)
        g_pidx16[s_off[l] + s_wcnt[w][l] + rank_in_warp] = (unsigned short)tid;
    if (tid <= NUM_L) g_off[tid] = s_off[tid];
    if (tid <  NUM_L) g_invcap[tid] = 1.0f / (cap[tid] + 1e-8f);
}

// ---------------------------------------------------------------------------
// Main: one block = 32 rows. Phase A: cp.async stage-in (no LDG->STS latency).
// Phase B: warp = link, lane = row, all LDS conflict-free (793/99 odd strides,
// index loads warp-uniform broadcasts). Then per-row stats + block partial.
// ---------------------------------------------------------------------------
__global__ __launch_bounds__(THREADS, 2)
void llb_main_kernel(const float* __restrict__ pred,
                     const float* __restrict__ dem) {
    extern __shared__ float smem[];
    float* sh_pred = smem;                       // ROWS * PSTRIDE floats
    float* sh_dem  = smem + ROWS * PSTRIDE;      // ROWS * NUM_D floats (reused as u)
    unsigned short* sh_idx = (unsigned short*)(sh_dem + ROWS * NUM_D);  // 792 u16

    const int tid  = threadIdx.x;
    const long long tile = blockIdx.x;
    const int link = tid >> 5;
    const int row  = tid & 31;

    // CSR metadata loads issued early (L2 latency overlapped with staging)
    const int   beg  = g_off[link];
    const int   end  = g_off[link + 1];
    const float invc = g_invcap[link];

    const float* gp = pred + tile * (ROWS * NUM_T);
    const float* gd = dem  + tile * (ROWS * NUM_D);
    const unsigned sp = (unsigned)__cvta_generic_to_shared(sh_pred);
    const unsigned sd = (unsigned)__cvta_generic_to_shared(sh_dem);

    // ---- Phase A: async stage-in ----
    #pragma unroll 8
    for (int i = tid; i < ROWS * NUM_T; i += THREADS) {
        int r = i / NUM_T;               // row*793 + col == i + r
        asm volatile("cp.async.ca.shared.global [%0], [%1], 4;"
                     :: "r"(sp + 4u * (unsigned)(i + r)), "l"(gp + i));
    }
    #pragma unroll
    for (int i = tid; i < ROWS * NUM_D; i += THREADS) {
        asm volatile("cp.async.ca.shared.global [%0], [%1], 4;"
                     :: "r"(sd + 4u * (unsigned)i), "l"(gd + i));
    }
    asm volatile("cp.async.commit_group;");

    // stage CSR indices while async copies are in flight
    sh_idx[tid < NUM_T ? tid : 0] = g_pidx16[tid < NUM_T ? tid : 0];
    {
        int t2 = tid + THREADS;
        if (t2 < NUM_T) sh_idx[t2] = g_pidx16[t2];
    }

    asm volatile("cp.async.wait_group 0;");
    __syncthreads();

    // ---- Phase B: per-(row,link) sums ----
    const float* pr = sh_pred + row * PSTRIDE;
    const float* dm = sh_dem  + row * NUM_D;

    float s0 = 0.f, s1 = 0.f, s2 = 0.f, s3 = 0.f;
    int j = beg;
    for (; j + 3 < end; j += 4) {
        int t0 = sh_idx[j];
        int t1 = sh_idx[j + 1];
        int t2 = sh_idx[j + 2];
        int t3 = sh_idx[j + 3];
        s0 += pr[t0] * dm[t0 >> 3];
        s1 += pr[t1] * dm[t1 >> 3];
        s2 += pr[t2] * dm[t2 >> 3];
        s3 += pr[t3] * dm[t3 >> 3];
    }
    for (; j < end; j++) {
        int t = sh_idx[j];
        s0 += pr[t] * dm[t >> 3];
    }
    const float u = ((s0 + s1) + (s2 + s3)) * invc;

    __syncthreads();                    // everyone done reading sh_dem
    float* sh_u = sh_dem;               // reuse: [ROWS][17] padded
    sh_u[row * 17 + link] = u;
    __syncthreads();

    // ---- per-row stats by warp 0 (lane = row) ----
    if (tid < 32) {
        const int r = tid;
        float ssum = 0.f, mx = -1e30f;
        #pragma unroll
        for (int l = 0; l < NUM_L; l++) {
            float x = sh_u[r * 17 + l];
            ssum += x;
            mx = fmaxf(mx, x);
        }
        const float mean = ssum * (1.0f / NUM_L);
        float var = 0.f;
        #pragma unroll
        for (int l = 0; l < NUM_L; l++) {
            float d = sh_u[r * 17 + l] - mean;
            var += d * d;
        }
        var *= (1.0f / (NUM_L - 1));    // ddof = 1
        float part = var + 0.5f * mx;
        #pragma unroll
        for (int o = 16; o > 0; o >>= 1)
            part += __shfl_down_sync(0xFFFFFFFFu, part, o);
        if (tid == 0) g_partials[blockIdx.x] = part;
    }
}

// ---------------------------------------------------------------------------
// Deterministic final reduction: 1 block, fixed-order strided + tree.
// ---------------------------------------------------------------------------
__global__ void llb_reduce_kernel(float* __restrict__ out, int nblocks, float inv_batch) {
    __shared__ float sb[1024];
    const int tid = threadIdx.x;
    float v = 0.f;
    for (int i = tid; i < nblocks; i += 1024)
        v += g_partials[i];
    sb[tid] = v;
    __syncthreads();
    #pragma unroll
    for (int s = 512; s > 0; s >>= 1) {
        if (tid < s) sb[tid] += sb[tid + s];
        __syncthreads();
    }
    if (tid == 0) out[0] = sb[0] * inv_batch;
}

extern "C" void kernel_launch(void* const* d_in, const int* in_sizes, int n_in,
                              void* d_out, int out_size) {
    const float* pred = (const float*)d_in[0];   // [B, 792]
    const float* dem  = (const float*)d_in[1];   // [B, 99]
    const int*   t2l  = (const int*)d_in[2];     // [792]
    const float* cap  = (const float*)d_in[3];   // [16]
    float* out = (float*)d_out;

    const int B = in_sizes[1] / NUM_D;           // 65536
    const int nblocks = B / ROWS;                // 2048

    static bool attr_set = false;
    const int smem_bytes = (ROWS * PSTRIDE + ROWS * NUM_D) * (int)sizeof(float)
                           + NUM_T * (int)sizeof(unsigned short);  // 115760
    if (!attr_set) {
        cudaFuncSetAttribute(llb_main_kernel,
                             cudaFuncAttributeMaxDynamicSharedMemorySize, smem_bytes);
        attr_set = true;
    }

    llb_setup_kernel<<<1, SETUP_THREADS>>>(t2l, cap);
    llb_main_kernel<<<nblocks, THREADS, smem_bytes>>>(pred, dem);
    llb_reduce_kernel<<<1, 1024>>>(out, nblocks, 1.0f / (float)B);
}